// round 4
// baseline (speedup 1.0000x reference)
#include <cuda_runtime.h>
#include <cuda_bf16.h>

#define XS 72
#define WSTR 72
#define CS 132

__device__ __align__(16) __nv_bfloat16 g_whi[16*64*64];
__device__ __align__(16) __nv_bfloat16 g_wlo[16*64*64];

__global__ void prep_w(const float* w) {
    int i = blockIdx.x*256 + threadIdx.x;        // over F*C*WW = 65536, layout [f][c][k]
    int k = i & 15, c = (i >> 4) & 63, f = i >> 10;
    float v = w[i];
    __nv_bfloat16 h = __float2bfloat16(v);
    int o = k*4096 + f*64 + c;
    g_whi[o] = h;
    g_wlo[o] = __float2bfloat16(v - __bfloat162float(h));
}

__device__ __forceinline__ void cpa16(void* s, const void* g) {
    unsigned sa;
    asm("{.reg .u64 t; cvta.to.shared.u64 t,%1; cvt.u32.u64 %0,t;}" : "=r"(sa) : "l"(s));
    asm volatile("cp.async.ca.shared.global [%0],[%1],16;" :: "r"(sa), "l"(g));
}

__device__ __forceinline__ void mma16(float* c, const unsigned* a, const unsigned* b) {
    asm volatile("mma.sync.aligned.m16n8k16.row.col.f32.bf16.bf16.f32 "
        "{%0,%1,%2,%3},{%4,%5,%6,%7},{%8,%9},{%0,%1,%2,%3};"
        : "+f"(c[0]), "+f"(c[1]), "+f"(c[2]), "+f"(c[3])
        : "r"(a[0]), "r"(a[1]), "r"(a[2]), "r"(a[3]), "r"(b[0]), "r"(b[1]));
}

__device__ __forceinline__ void stage_w(__nv_bfloat16* wsm, int k, int s, int tid) {
    #pragma unroll
    for (int r = 0; r < 2; r++) {
        int i = r*256 + tid;                      // 0..511
        int f = i >> 3, seg = i & 7;
        cpa16(wsm + s*(2*64*WSTR) + f*WSTR + seg*8,          g_whi + k*4096 + f*64 + seg*8);
        cpa16(wsm + s*(2*64*WSTR) + 64*WSTR + f*WSTR + seg*8, g_wlo + k*4096 + f*64 + seg*8);
    }
    asm volatile("cp.async.commit_group;" ::: "memory");
}

extern __shared__ unsigned char smraw[];

__global__ void __launch_bounds__(256, 1)
conv_main(const float* __restrict__ x, const float* __restrict__ bias, float* __restrict__ out) {
    const int t0 = blockIdx.x * 128;
    const int n  = blockIdx.y;
    const int tid = threadIdx.x;
    __nv_bfloat16* xhi = (__nv_bfloat16*)smraw;            // [144][XS]
    __nv_bfloat16* xlo = xhi + 144*XS;
    __nv_bfloat16* wsm = xlo + 144*XS;                     // [2][2][64][WSTR]
    float* csm = (float*)smraw;                            // [64][CS], epilogue only

    const float* xb = x + n*64*4096;
    for (int i = tid; i < 64*144; i += 256) {
        int c = i / 144, t = i - c*144;
        int tg = t0 + t;
        float v = (tg < 4096) ? xb[c*4096 + tg] : 0.f;
        __nv_bfloat16 h = __float2bfloat16(v);
        xhi[t*XS + c] = h;
        xlo[t*XS + c] = __float2bfloat16(v - __bfloat162float(h));
    }

    const int wid = tid >> 5, lane = tid & 31;
    const int wm = wid >> 1, wn = wid & 1;
    const int g = lane >> 2, tq = lane & 3;
    float acc[2][4][4] = {};

    stage_w(wsm, 0, 0, tid);
    asm volatile("cp.async.wait_group 0;" ::: "memory");
    __syncthreads();

    for (int k = 0; k < 16; k++) {
        int s = k & 1;
        if (k < 15) stage_w(wsm, k + 1, s ^ 1, tid);
        const __nv_bfloat16* wh = wsm + s*(2*64*WSTR);
        const __nv_bfloat16* wl = wh + 64*WSTR;
        #pragma unroll
        for (int cc = 0; cc < 64; cc += 16) {
            unsigned ah[2][4], al[2][4];
            #pragma unroll
            for (int mt = 0; mt < 2; mt++) {
                int r = wm*32 + mt*16 + g + k;
                int cw = cc + 2*tq;
                ah[mt][0] = *(const unsigned*)&xhi[r*XS + cw];
                ah[mt][1] = *(const unsigned*)&xhi[(r+8)*XS + cw];
                ah[mt][2] = *(const unsigned*)&xhi[r*XS + cw + 8];
                ah[mt][3] = *(const unsigned*)&xhi[(r+8)*XS + cw + 8];
                al[mt][0] = *(const unsigned*)&xlo[r*XS + cw];
                al[mt][1] = *(const unsigned*)&xlo[(r+8)*XS + cw];
                al[mt][2] = *(const unsigned*)&xlo[r*XS + cw + 8];
                al[mt][3] = *(const unsigned*)&xlo[(r+8)*XS + cw + 8];
            }
            #pragma unroll
            for (int nt = 0; nt < 4; nt++) {
                int f = wn*32 + nt*8 + g;
                int cw = cc + 2*tq;
                unsigned bh[2], bl[2];
                bh[0] = *(const unsigned*)&wh[f*WSTR + cw];
                bh[1] = *(const unsigned*)&wh[f*WSTR + cw + 8];
                bl[0] = *(const unsigned*)&wl[f*WSTR + cw];
                bl[1] = *(const unsigned*)&wl[f*WSTR + cw + 8];
                #pragma unroll
                for (int mt = 0; mt < 2; mt++) {
                    mma16(acc[mt][nt], ah[mt], bh);
                    mma16(acc[mt][nt], al[mt], bh);
                    mma16(acc[mt][nt], ah[mt], bl);
                }
            }
        }
        asm volatile("cp.async.wait_group 0;" ::: "memory");
        __syncthreads();
    }

    // epilogue: transpose through smem (reuses x region), coalesced stores
    #pragma unroll
    for (int mt = 0; mt < 2; mt++)
        #pragma unroll
        for (int nt = 0; nt < 4; nt++) {
            int f = wn*32 + nt*8 + 2*tq;
            int r = wm*32 + mt*16 + g;
            csm[f*CS + r]           = acc[mt][nt][0];
            csm[(f+1)*CS + r]       = acc[mt][nt][1];
            csm[f*CS + r + 8]       = acc[mt][nt][2];
            csm[(f+1)*CS + r + 8]   = acc[mt][nt][3];
        }
    __syncthreads();
    float* ob = out + n*64*4081;
    for (int i = tid; i < 64*128; i += 256) {
        int f = i >> 7, t = i & 127;
        int tg = t0 + t;
        if (tg < 4081) ob[f*4081 + tg] = csm[f*CS + t] + bias[f];
    }
}

extern "C" void kernel_launch(void* const* d_in, const int* in_sizes, int n_in,
                              void* d_out, int out_size) {
    const float* x = (const float*)d_in[0];
    const float* w = (const float*)d_in[1];
    const float* b = (const float*)d_in[2];
    float* out = (float*)d_out;
    (void)in_sizes; (void)n_in; (void)out_size;

    static const int SMEM = (2*144*XS + 2*2*64*WSTR) * 2;   // 78336 bytes
    cudaFuncSetAttribute(conv_main, cudaFuncAttributeMaxDynamicSharedMemorySize, SMEM);

    prep_w<<<256, 256>>>(w);
    conv_main<<<dim3(32, 64), 256, SMEM>>>(x, b, out);
}